// round 11
// baseline (speedup 1.0000x reference)
#include <cuda_runtime.h>
#include <cuda_bf16.h>
#include <cstdint>

#define N_NODES 50000
#define DIM 128
#define N_EDGES 800000
#define N_OUT 47

// ---------------- scratch (device globals; no allocation allowed) ----------------
// packed split-bf16: value = hi + lo (hi = bf16(x), lo = bf16(x - hi))
__device__ __align__(16) __nv_bfloat16 g_hHi[N_NODES * DIM];   // h (node features, packed)
__device__ __align__(16) __nv_bfloat16 g_hLo[N_NODES * DIM];
__device__ __align__(16) __nv_bfloat16 g_pHi[N_NODES * DIM];   // p = h @ Wn^T (packed)
__device__ __align__(16) __nv_bfloat16 g_pLo[N_NODES * DIM];
__device__ __align__(16) float g_self[N_NODES * DIM];          // h @ Ws^T + b (fp32)
__device__ int   g_rowptr[N_NODES + 1];
__device__ __align__(16) int g_cursor[N_NODES];
__device__ int   g_esrc[N_EDGES];
__device__ __align__(16) __nv_bfloat16 g_Bhi[256 * 128];       // stacked [Ws|Wn] hi
__device__ __align__(16) __nv_bfloat16 g_Blo[256 * 128];       // stacked [Ws|Wn] lo

// ---------------- helpers ----------------

__device__ __forceinline__ uint32_t pack_bf16(__nv_bfloat16 l, __nv_bfloat16 h) {
    return ((uint32_t)__bfloat16_as_ushort(h) << 16) | __bfloat16_as_ushort(l);
}
__device__ __forceinline__ float bf_lo(uint32_t w) { return __uint_as_float(w << 16); }
__device__ __forceinline__ float bf_hi(uint32_t w) { return __uint_as_float(w & 0xFFFF0000u); }

__device__ __forceinline__ void split2(float v0, float v1, uint32_t& hi, uint32_t& lo) {
    __nv_bfloat16 h0 = __float2bfloat16(v0), h1 = __float2bfloat16(v1);
    __nv_bfloat16 l0 = __float2bfloat16(v0 - __bfloat162float(h0));
    __nv_bfloat16 l1 = __float2bfloat16(v1 - __bfloat162float(h1));
    hi = pack_bf16(h0, h1);
    lo = pack_bf16(l0, l1);
}

__device__ __forceinline__ void ldsm4(uint32_t* r, uint32_t addr) {
    asm volatile("ldmatrix.sync.aligned.m8n8.x4.shared.b16 {%0,%1,%2,%3}, [%4];"
        : "=r"(r[0]), "=r"(r[1]), "=r"(r[2]), "=r"(r[3]) : "r"(addr));
}

// ---------------- CSR build (by dst), 4 edges/thread ----------------

__global__ void zero_cursor_k() {
    int i = blockIdx.x * blockDim.x + threadIdx.x;
    if (i < N_NODES / 4) ((int4*)g_cursor)[i] = make_int4(0, 0, 0, 0);
}
__global__ void count_k(const int* __restrict__ dst) {
    int t = blockIdx.x * blockDim.x + threadIdx.x;
    if (t < N_EDGES / 4) {
        int4 d = ((const int4*)dst)[t];
        atomicAdd(&g_cursor[d.x], 1);
        atomicAdd(&g_cursor[d.y], 1);
        atomicAdd(&g_cursor[d.z], 1);
        atomicAdd(&g_cursor[d.w], 1);
    }
}
__global__ void scan_k() {
    __shared__ int ssum[1024];
    int t = threadIdx.x;
    const int CH = (N_NODES + 1023) / 1024;
    int base = t * CH;
    int s = 0;
    for (int i = 0; i < CH; i++) { int idx = base + i; if (idx < N_NODES) s += g_cursor[idx]; }
    ssum[t] = s;
    __syncthreads();
    for (int off = 1; off < 1024; off <<= 1) {
        int v = 0;
        if (t >= off) v = ssum[t - off];
        __syncthreads();
        if (t >= off) ssum[t] += v;
        __syncthreads();
    }
    int run = (t == 0) ? 0 : ssum[t - 1];
    for (int i = 0; i < CH; i++) {
        int idx = base + i;
        if (idx < N_NODES) {
            int c = g_cursor[idx];
            g_rowptr[idx] = run;
            g_cursor[idx] = run;
            run += c;
        }
    }
    if (t == 0) g_rowptr[N_NODES] = N_EDGES;
}
__global__ void bucket_k(const int* __restrict__ src, const int* __restrict__ dst) {
    int t = blockIdx.x * blockDim.x + threadIdx.x;
    if (t < N_EDGES / 4) {
        int4 s = ((const int4*)src)[t];
        int4 d = ((const int4*)dst)[t];
        g_esrc[atomicAdd(&g_cursor[d.x], 1)] = s.x;
        g_esrc[atomicAdd(&g_cursor[d.y], 1)] = s.y;
        g_esrc[atomicAdd(&g_cursor[d.z], 1)] = s.z;
        g_esrc[atomicAdd(&g_cursor[d.w], 1)] = s.w;
    }
}

// ---------------- B prep: stacked [Ws ; Wn] -> hi/lo bf16 [2*NT][128] ----------------

__global__ void prepB_k(const float* __restrict__ ws, const float* __restrict__ wn,
                        int nout, int NT) {
    int idx = blockIdx.x * blockDim.x + threadIdx.x;
    if (idx >= 2 * NT * 128) return;
    int n = idx / 128, k = idx % 128;
    float v = 0.f;
    if (n < NT) { if (n < nout) v = ws[n * 128 + k]; }
    else        { int m = n - NT; if (m < nout) v = wn[m * 128 + k]; }
    __nv_bfloat16 h = __float2bfloat16(v);
    __nv_bfloat16 l = __float2bfloat16(v - __bfloat162float(h));
    g_Bhi[idx] = h;
    g_Blo[idx] = l;
}

// ---------------- fused aggregate+combine: h = relu(self + mean(p)) ----------------
// one warp per node; p packed hi/lo stride 128; writes packed h

__global__ void agg12_k(const __nv_bfloat16* __restrict__ pHi,
                        const __nv_bfloat16* __restrict__ pLo,
                        const float* __restrict__ self,
                        __nv_bfloat16* __restrict__ outHi,
                        __nv_bfloat16* __restrict__ outLo) {
    int gt = blockIdx.x * blockDim.x + threadIdx.x;
    int node = gt >> 5, lane = gt & 31;
    if (node >= N_NODES) return;
    int beg = g_rowptr[node], end = g_rowptr[node + 1];
    float a0 = 0.f, a1 = 0.f, a2 = 0.f, a3 = 0.f;
    float c0 = 0.f, c1 = 0.f, c2 = 0.f, c3 = 0.f;
    int j = beg;
    for (; j + 1 < end; j += 2) {
        int s0 = g_esrc[j], s1 = g_esrc[j + 1];
        uint2 h0 = *(const uint2*)(pHi + (size_t)s0 * DIM + lane * 4);
        uint2 l0 = *(const uint2*)(pLo + (size_t)s0 * DIM + lane * 4);
        uint2 h1 = *(const uint2*)(pHi + (size_t)s1 * DIM + lane * 4);
        uint2 l1 = *(const uint2*)(pLo + (size_t)s1 * DIM + lane * 4);
        a0 += bf_lo(h0.x) + bf_lo(l0.x); a1 += bf_hi(h0.x) + bf_hi(l0.x);
        a2 += bf_lo(h0.y) + bf_lo(l0.y); a3 += bf_hi(h0.y) + bf_hi(l0.y);
        c0 += bf_lo(h1.x) + bf_lo(l1.x); c1 += bf_hi(h1.x) + bf_hi(l1.x);
        c2 += bf_lo(h1.y) + bf_lo(l1.y); c3 += bf_hi(h1.y) + bf_hi(l1.y);
    }
    if (j < end) {
        int s0 = g_esrc[j];
        uint2 h0 = *(const uint2*)(pHi + (size_t)s0 * DIM + lane * 4);
        uint2 l0 = *(const uint2*)(pLo + (size_t)s0 * DIM + lane * 4);
        a0 += bf_lo(h0.x) + bf_lo(l0.x); a1 += bf_hi(h0.x) + bf_hi(l0.x);
        a2 += bf_lo(h0.y) + bf_lo(l0.y); a3 += bf_hi(h0.y) + bf_hi(l0.y);
    }
    float inv = 1.f / fmaxf((float)(end - beg), 1.f);
    float4 sv = *(const float4*)(self + (size_t)node * DIM + lane * 4);
    a0 = fmaxf((a0 + c0) * inv + sv.x, 0.f);
    a1 = fmaxf((a1 + c1) * inv + sv.y, 0.f);
    a2 = fmaxf((a2 + c2) * inv + sv.z, 0.f);
    a3 = fmaxf((a3 + c3) * inv + sv.w, 0.f);
    uint32_t h01, l01, h23, l23;
    split2(a0, a1, h01, l01);
    split2(a2, a3, h23, l23);
    size_t off = (size_t)node * DIM + lane * 4;
    *(uint32_t*)(outHi + off) = h01;
    *(uint32_t*)(outHi + off + 2) = h23;
    *(uint32_t*)(outLo + off) = l01;
    *(uint32_t*)(outLo + off + 2) = l23;
}

// layer 3: p stride 64 (47 valid), out = self + mean(p), fp32 [N,47]
__global__ void agg3_k(const __nv_bfloat16* __restrict__ pHi,
                       const __nv_bfloat16* __restrict__ pLo,
                       const float* __restrict__ self,
                       float* __restrict__ out) {
    int gt = blockIdx.x * blockDim.x + threadIdx.x;
    int node = gt >> 5, lane = gt & 31;
    if (node >= N_NODES) return;
    int beg = g_rowptr[node], end = g_rowptr[node + 1];
    float a0 = 0.f, a1 = 0.f, c0 = 0.f, c1 = 0.f;
    int j = beg;
    for (; j + 1 < end; j += 2) {
        int s0 = g_esrc[j], s1 = g_esrc[j + 1];
        uint32_t h0 = *(const uint32_t*)(pHi + (size_t)s0 * 64 + lane * 2);
        uint32_t l0 = *(const uint32_t*)(pLo + (size_t)s0 * 64 + lane * 2);
        uint32_t h1 = *(const uint32_t*)(pHi + (size_t)s1 * 64 + lane * 2);
        uint32_t l1 = *(const uint32_t*)(pLo + (size_t)s1 * 64 + lane * 2);
        a0 += bf_lo(h0) + bf_lo(l0); a1 += bf_hi(h0) + bf_hi(l0);
        c0 += bf_lo(h1) + bf_lo(l1); c1 += bf_hi(h1) + bf_hi(l1);
    }
    if (j < end) {
        int s0 = g_esrc[j];
        uint32_t h0 = *(const uint32_t*)(pHi + (size_t)s0 * 64 + lane * 2);
        uint32_t l0 = *(const uint32_t*)(pLo + (size_t)s0 * 64 + lane * 2);
        a0 += bf_lo(h0) + bf_lo(l0); a1 += bf_hi(h0) + bf_hi(l0);
    }
    float inv = 1.f / fmaxf((float)(end - beg), 1.f);
    float v0 = (a0 + c0) * inv + self[(size_t)node * 64 + lane * 2];
    float v1 = (a1 + c1) * inv + self[(size_t)node * 64 + lane * 2 + 1];
    int col = lane * 2;
    if (col < N_OUT)     out[(size_t)node * N_OUT + col]     = v0;
    if (col + 1 < N_OUT) out[(size_t)node * N_OUT + col + 1] = v1;
}

// ---------------- mma.sync split-bf16 GEMM: [self+b | p] = h @ [Ws|Wn]^T ----------------
// K=128, CTA tile 128x128. grid.y: 0 -> self half, 1 -> p half (L3: single CTA, wn-split).

__device__ __forceinline__ void mma16816(float* c, const uint32_t* a, const uint32_t* b) {
    asm volatile(
        "mma.sync.aligned.m16n8k16.row.col.f32.bf16.bf16.f32 "
        "{%0,%1,%2,%3}, {%4,%5,%6,%7}, {%8,%9}, {%0,%1,%2,%3};"
        : "+f"(c[0]), "+f"(c[1]), "+f"(c[2]), "+f"(c[3])
        : "r"(a[0]), "r"(a[1]), "r"(a[2]), "r"(a[3]), "r"(b[0]), "r"(b[1]));
}

#define BKP 40  // padded row: 32 bf16 + 8 (stride 80B -> conflict-free LDS/LDSM)

template <bool L1IN, bool L3>
__global__ void __launch_bounds__(256) gemm_mma(
    const float* __restrict__ xf,
    const __nv_bfloat16* __restrict__ Ahi, const __nv_bfloat16* __restrict__ Alo,
    const float* __restrict__ bias, int biasN,
    float* __restrict__ outSelf,
    __nv_bfloat16* __restrict__ outPHi, __nv_bfloat16* __restrict__ outPLo) {
    constexpr int NF = 8;
    __shared__ __align__(16) uint16_t As_hi[128][BKP];
    __shared__ __align__(16) uint16_t As_lo[128][BKP];
    __shared__ __align__(16) uint16_t Bs_hi[128][BKP];
    __shared__ __align__(16) uint16_t Bs_lo[128][BKP];

    int tid = threadIdx.x;
    int warp = tid >> 5, lane = tid & 31;
    int wm = warp & 3, wn = warp >> 2;
    int qrow = lane >> 2, qk2 = (lane & 3) * 2;
    int rowBase = blockIdx.x * 128;
    int nOff = blockIdx.y * 128;

    float c[2][NF][4];
#pragma unroll
    for (int mi = 0; mi < 2; mi++)
#pragma unroll
        for (int ni = 0; ni < NF; ni++)
#pragma unroll
            for (int j = 0; j < 4; j++) c[mi][ni][j] = 0.f;

    int g = lane >> 3, l = lane & 7;
    uint32_t aoff = (uint32_t)(((wm * 32 + ((g & 1) << 3) + l) * BKP + ((g >> 1) << 3)) * 2);
    uint32_t boff = (uint32_t)(((wn * 64 + ((g & 2) << 2) + l) * BKP + ((g & 1) << 3)) * 2);
    uint32_t aAddrHi = (uint32_t)__cvta_generic_to_shared(As_hi) + aoff;
    uint32_t aAddrLo = (uint32_t)__cvta_generic_to_shared(As_lo) + aoff;
    uint32_t bAddrHi = (uint32_t)__cvta_generic_to_shared(Bs_hi) + boff;
    uint32_t bAddrLo = (uint32_t)__cvta_generic_to_shared(Bs_lo) + boff;

    uint2 rah[4], ral[4], rbh[4], rbl[4];

    auto loadA = [&](int kb) {
        if (L1IN) {
#pragma unroll
            for (int i = 0; i < 4; i++) {
                int idx = tid + i * 256;
                int r = idx >> 3, u = idx & 7;
                int gr = rowBase + r;
                if (gr >= N_NODES) gr = N_NODES - 1;
                float4 v = *(const float4*)(xf + (size_t)gr * 128 + kb + u * 4);
                split2(v.x, v.y, rah[i].x, ral[i].x);
                split2(v.z, v.w, rah[i].y, ral[i].y);
            }
        } else {
#pragma unroll
            for (int i = 0; i < 4; i++) {
                int idx = tid + i * 256;
                int r = idx >> 3, u = idx & 7;
                int gr = rowBase + r;
                if (gr >= N_NODES) gr = N_NODES - 1;
                rah[i] = *(const uint2*)(Ahi + (size_t)gr * 128 + kb + u * 4);
                ral[i] = *(const uint2*)(Alo + (size_t)gr * 128 + kb + u * 4);
            }
        }
    };
    auto loadB = [&](int kb) {
#pragma unroll
        for (int i = 0; i < 4; i++) {
            int idx = tid + i * 256;
            int n = idx >> 3, u = idx & 7;
            rbh[i] = *(const uint2*)(g_Bhi + (nOff + n) * 128 + kb + u * 4);
            rbl[i] = *(const uint2*)(g_Blo + (nOff + n) * 128 + kb + u * 4);
        }
    };

    loadA(0);
    loadB(0);

    for (int t = 0; t < 4; t++) {
        int kb = t * 32;
        __syncthreads();
#pragma unroll
        for (int i = 0; i < 4; i++) {
            int idx = tid + i * 256;
            int r = idx >> 3, u = idx & 7;
            *(uint2*)&As_hi[r][u * 4] = rah[i];
            *(uint2*)&As_lo[r][u * 4] = ral[i];
            *(uint2*)&Bs_hi[r][u * 4] = rbh[i];
            *(uint2*)&Bs_lo[r][u * 4] = rbl[i];
        }
        __syncthreads();
        if (t < 3) { loadA(kb + 32); loadB(kb + 32); }

#pragma unroll
        for (int kk = 0; kk < 2; kk++) {
            uint32_t koff = kk * 32;
            uint32_t a_hi[2][4], a_lo[2][4];
#pragma unroll
            for (int mi = 0; mi < 2; mi++) {
                ldsm4(a_hi[mi], aAddrHi + mi * (16 * BKP * 2) + koff);
                ldsm4(a_lo[mi], aAddrLo + mi * (16 * BKP * 2) + koff);
            }
#pragma unroll
            for (int nj = 0; nj < NF / 2; nj++) {
                uint32_t bh[4], bl[4];
                ldsm4(bh, bAddrHi + nj * (16 * BKP * 2) + koff);
                ldsm4(bl, bAddrLo + nj * (16 * BKP * 2) + koff);
#pragma unroll
                for (int hh = 0; hh < 2; hh++) {
                    int ni = nj * 2 + hh;
#pragma unroll
                    for (int mi = 0; mi < 2; mi++) {
                        mma16816(c[mi][ni], a_hi[mi], bh + hh * 2);
                        mma16816(c[mi][ni], a_hi[mi], bl + hh * 2);
                        mma16816(c[mi][ni], a_lo[mi], bh + hh * 2);
                    }
                }
            }
        }
    }

    // ---- epilogue: self half -> fp32 (+bias); p half -> packed hi/lo ----
    const int stride = L3 ? 64 : 128;
#pragma unroll
    for (int mi = 0; mi < 2; mi++) {
        int r0 = rowBase + wm * 32 + mi * 16 + qrow;
#pragma unroll
        for (int ni = 0; ni < NF; ni++) {
            int col = wn * 64 + ni * 8 + qk2;
            bool selfHalf = L3 ? (col < 64) : (blockIdx.y == 0);
            float v0 = c[mi][ni][0], v1 = c[mi][ni][1];
            float v2 = c[mi][ni][2], v3 = c[mi][ni][3];
            if (selfHalf) {
                int scol = col;  // L3: 0..63, L12: 0..127
                float b0 = (scol < biasN) ? bias[scol] : 0.f;
                float b1 = (scol + 1 < biasN) ? bias[scol + 1] : 0.f;
                v0 += b0; v1 += b1; v2 += b0; v3 += b1;
                if (r0 < N_NODES) {
                    outSelf[(size_t)r0 * stride + scol] = v0;
                    outSelf[(size_t)r0 * stride + scol + 1] = v1;
                }
                if (r0 + 8 < N_NODES) {
                    outSelf[(size_t)(r0 + 8) * stride + scol] = v2;
                    outSelf[(size_t)(r0 + 8) * stride + scol + 1] = v3;
                }
            } else {
                int pcol = L3 ? (col - 64) : col;
                if (r0 < N_NODES) {
                    uint32_t hi, lo;
                    split2(v0, v1, hi, lo);
                    *(uint32_t*)(outPHi + (size_t)r0 * stride + pcol) = hi;
                    *(uint32_t*)(outPLo + (size_t)r0 * stride + pcol) = lo;
                }
                if (r0 + 8 < N_NODES) {
                    uint32_t hi, lo;
                    split2(v2, v3, hi, lo);
                    *(uint32_t*)(outPHi + (size_t)(r0 + 8) * stride + pcol) = hi;
                    *(uint32_t*)(outPLo + (size_t)(r0 + 8) * stride + pcol) = lo;
                }
            }
        }
    }
}

// ---------------- launch ----------------

extern "C" void kernel_launch(void* const* d_in, const int* in_sizes, int n_in,
                              void* d_out, int out_size) {
    const float* x   = (const float*)d_in[0];
    const int*   src = (const int*)d_in[1];
    const int*   dst = (const int*)d_in[2];
    const float* ws1 = (const float*)d_in[3];
    const float* wn1 = (const float*)d_in[4];
    const float* b1  = (const float*)d_in[5];
    const float* ws2 = (const float*)d_in[6];
    const float* wn2 = (const float*)d_in[7];
    const float* b2  = (const float*)d_in[8];
    const float* ws3 = (const float*)d_in[9];
    const float* wn3 = (const float*)d_in[10];
    const float* b3  = (const float*)d_in[11];
    float* out = (float*)d_out;

    void *phh, *phl, *pph, *ppl, *psf;
    cudaGetSymbolAddress(&phh, g_hHi);
    cudaGetSymbolAddress(&phl, g_hLo);
    cudaGetSymbolAddress(&pph, g_pHi);
    cudaGetSymbolAddress(&ppl, g_pLo);
    cudaGetSymbolAddress(&psf, g_self);
    __nv_bfloat16* hHi = (__nv_bfloat16*)phh;
    __nv_bfloat16* hLo = (__nv_bfloat16*)phl;
    __nv_bfloat16* pHi = (__nv_bfloat16*)pph;
    __nv_bfloat16* pLo = (__nv_bfloat16*)ppl;
    float* selfb = (float*)psf;

    const int E4B = (N_EDGES / 4 + 255) / 256;
    const int ZB = (N_NODES / 4 + 255) / 256;
    const int AGG_B = (N_NODES * 32 + 255) / 256;
    const int GEMM_X = (N_NODES + 127) / 128;

    // CSR build
    zero_cursor_k<<<ZB, 256>>>();
    count_k<<<E4B, 256>>>(dst);
    scan_k<<<1, 1024>>>();
    bucket_k<<<E4B, 256>>>(src, dst);

    // Layer 1: [self1 | p1] = x @ [Ws1|Wn1]^T ; h1 = relu(self1 + mean(p1))
    prepB_k<<<(2 * 128 * 128 + 255) / 256, 256>>>(ws1, wn1, 128, 128);
    gemm_mma<true, false><<<dim3(GEMM_X, 2), 256>>>(
        x, nullptr, nullptr, b1, 128, selfb, pHi, pLo);
    agg12_k<<<AGG_B, 256>>>(pHi, pLo, selfb, hHi, hLo);

    // Layer 2
    prepB_k<<<(2 * 128 * 128 + 255) / 256, 256>>>(ws2, wn2, 128, 128);
    gemm_mma<false, false><<<dim3(GEMM_X, 2), 256>>>(
        nullptr, hHi, hLo, b2, 128, selfb, pHi, pLo);
    agg12_k<<<AGG_B, 256>>>(pHi, pLo, selfb, hHi, hLo);

    // Layer 3: [self3 | p3] (47-wide halves, 64-padded), out = self3 + mean(p3)
    prepB_k<<<(2 * 64 * 128 + 255) / 256, 256>>>(ws3, wn3, N_OUT, 64);
    gemm_mma<false, true><<<dim3(GEMM_X, 1), 256>>>(
        nullptr, hHi, hLo, b3, N_OUT, selfb, pHi, pLo);
    agg3_k<<<AGG_B, 256>>>(pHi, pLo, selfb, out);
}

// round 13
// speedup vs baseline: 1.0999x; 1.0999x over previous
#include <cuda_runtime.h>
#include <cuda_bf16.h>
#include <cstdint>

#define N_NODES 50000
#define DIM 128
#define N_EDGES 800000
#define N_OUT 47

// ---------------- scratch (device globals; no allocation allowed) ----------------
// features stored as split bf16: value = hi + lo  (hi = bf16(x), lo = bf16(x - hi))
__device__ __align__(16) __nv_bfloat16 g_f0hi[N_NODES * DIM];
__device__ __align__(16) __nv_bfloat16 g_f0lo[N_NODES * DIM];
__device__ __align__(16) __nv_bfloat16 g_f1hi[N_NODES * DIM];
__device__ __align__(16) __nv_bfloat16 g_f1lo[N_NODES * DIM];
__device__ __align__(16) __nv_bfloat16 g_mhi[N_NODES * DIM];
__device__ __align__(16) __nv_bfloat16 g_mlo[N_NODES * DIM];
__device__ int   g_rowptr[N_NODES + 1];
__device__ __align__(16) int g_cursor[N_NODES];
__device__ int   g_esrc[N_EDGES];
__device__ __align__(16) __nv_bfloat16 g_B1hi[128 * 256];
__device__ __align__(16) __nv_bfloat16 g_B1lo[128 * 256];
__device__ __align__(16) __nv_bfloat16 g_B2hi[128 * 256];
__device__ __align__(16) __nv_bfloat16 g_B2lo[128 * 256];
__device__ __align__(16) __nv_bfloat16 g_B3hi[64 * 256];
__device__ __align__(16) __nv_bfloat16 g_B3lo[64 * 256];

// ---------------- helpers ----------------

__device__ __forceinline__ uint32_t pack_bf16(__nv_bfloat16 l, __nv_bfloat16 h) {
    return ((uint32_t)__bfloat16_as_ushort(h) << 16) | __bfloat16_as_ushort(l);
}
__device__ __forceinline__ float bf_lo(uint32_t w) { return __uint_as_float(w << 16); }
__device__ __forceinline__ float bf_hi(uint32_t w) { return __uint_as_float(w & 0xFFFF0000u); }

__device__ __forceinline__ void split2(float v0, float v1, uint32_t& hi, uint32_t& lo) {
    __nv_bfloat16 h0 = __float2bfloat16(v0), h1 = __float2bfloat16(v1);
    __nv_bfloat16 l0 = __float2bfloat16(v0 - __bfloat162float(h0));
    __nv_bfloat16 l1 = __float2bfloat16(v1 - __bfloat162float(h1));
    hi = pack_bf16(h0, h1);
    lo = pack_bf16(l0, l1);
}

__device__ __forceinline__ void ldsm4(uint32_t* r, uint32_t addr) {
    asm volatile("ldmatrix.sync.aligned.m8n8.x4.shared.b16 {%0,%1,%2,%3}, [%4];"
        : "=r"(r[0]), "=r"(r[1]), "=r"(r[2]), "=r"(r[3]) : "r"(addr));
}

// ---------------- CSR build (by dst) ----------------

__global__ void count_k(const int* __restrict__ dst) {
    int e = blockIdx.x * blockDim.x + threadIdx.x;
    if (e < N_EDGES) atomicAdd(&g_cursor[dst[e]], 1);
}
__global__ void scan_k() {
    __shared__ int ssum[1024];
    int t = threadIdx.x;
    const int CH = (N_NODES + 1023) / 1024;
    int base = t * CH;
    int s = 0;
    for (int i = 0; i < CH; i++) { int idx = base + i; if (idx < N_NODES) s += g_cursor[idx]; }
    ssum[t] = s;
    __syncthreads();
    for (int off = 1; off < 1024; off <<= 1) {
        int v = 0;
        if (t >= off) v = ssum[t - off];
        __syncthreads();
        if (t >= off) ssum[t] += v;
        __syncthreads();
    }
    int run = (t == 0) ? 0 : ssum[t - 1];
    for (int i = 0; i < CH; i++) {
        int idx = base + i;
        if (idx < N_NODES) {
            int c = g_cursor[idx];
            g_rowptr[idx] = run;
            g_cursor[idx] = run;
            run += c;
        }
    }
    if (t == 0) g_rowptr[N_NODES] = N_EDGES;
}
__global__ void bucket_k(const int* __restrict__ src, const int* __restrict__ dst) {
    int e = blockIdx.x * blockDim.x + threadIdx.x;
    if (e < N_EDGES) {
        int pos = atomicAdd(&g_cursor[dst[e]], 1);
        g_esrc[pos] = src[e];
    }
}

// ---------------- mean aggregation: one warp per node, 4-edge unroll; packed hi/lo mean out ----------------

template <bool GF32>
__global__ void agg_k(const float* __restrict__ xf,
                      const __nv_bfloat16* __restrict__ hhi,
                      const __nv_bfloat16* __restrict__ hlo) {
    int gt = blockIdx.x * blockDim.x + threadIdx.x;
    int node = gt >> 5, lane = gt & 31;
    if (node >= N_NODES) return;
    int beg = g_rowptr[node], end = g_rowptr[node + 1];
    float a0 = 0.f, a1 = 0.f, a2 = 0.f, a3 = 0.f;
    float c0 = 0.f, c1 = 0.f, c2 = 0.f, c3 = 0.f;
    int j = beg;
    if (GF32) {
        for (; j + 3 < end; j += 4) {
            int s0 = g_esrc[j], s1 = g_esrc[j + 1], s2 = g_esrc[j + 2], s3 = g_esrc[j + 3];
            float4 v0 = *(const float4*)(xf + (size_t)s0 * DIM + lane * 4);
            float4 v1 = *(const float4*)(xf + (size_t)s1 * DIM + lane * 4);
            float4 v2 = *(const float4*)(xf + (size_t)s2 * DIM + lane * 4);
            float4 v3 = *(const float4*)(xf + (size_t)s3 * DIM + lane * 4);
            a0 += v0.x; a1 += v0.y; a2 += v0.z; a3 += v0.w;
            c0 += v1.x; c1 += v1.y; c2 += v1.z; c3 += v1.w;
            a0 += v2.x; a1 += v2.y; a2 += v2.z; a3 += v2.w;
            c0 += v3.x; c1 += v3.y; c2 += v3.z; c3 += v3.w;
        }
        for (; j < end; j++) {
            int s0 = g_esrc[j];
            float4 v0 = *(const float4*)(xf + (size_t)s0 * DIM + lane * 4);
            a0 += v0.x; a1 += v0.y; a2 += v0.z; a3 += v0.w;
        }
    } else {
        for (; j + 3 < end; j += 4) {
            int s0 = g_esrc[j], s1 = g_esrc[j + 1], s2 = g_esrc[j + 2], s3 = g_esrc[j + 3];
            uint2 h0 = *(const uint2*)(hhi + (size_t)s0 * DIM + lane * 4);
            uint2 l0 = *(const uint2*)(hlo + (size_t)s0 * DIM + lane * 4);
            uint2 h1 = *(const uint2*)(hhi + (size_t)s1 * DIM + lane * 4);
            uint2 l1 = *(const uint2*)(hlo + (size_t)s1 * DIM + lane * 4);
            uint2 h2 = *(const uint2*)(hhi + (size_t)s2 * DIM + lane * 4);
            uint2 l2 = *(const uint2*)(hlo + (size_t)s2 * DIM + lane * 4);
            uint2 h3 = *(const uint2*)(hhi + (size_t)s3 * DIM + lane * 4);
            uint2 l3 = *(const uint2*)(hlo + (size_t)s3 * DIM + lane * 4);
            a0 += bf_lo(h0.x) + bf_lo(l0.x); a1 += bf_hi(h0.x) + bf_hi(l0.x);
            a2 += bf_lo(h0.y) + bf_lo(l0.y); a3 += bf_hi(h0.y) + bf_hi(l0.y);
            c0 += bf_lo(h1.x) + bf_lo(l1.x); c1 += bf_hi(h1.x) + bf_hi(l1.x);
            c2 += bf_lo(h1.y) + bf_lo(l1.y); c3 += bf_hi(h1.y) + bf_hi(l1.y);
            a0 += bf_lo(h2.x) + bf_lo(l2.x); a1 += bf_hi(h2.x) + bf_hi(l2.x);
            a2 += bf_lo(h2.y) + bf_lo(l2.y); a3 += bf_hi(h2.y) + bf_hi(l2.y);
            c0 += bf_lo(h3.x) + bf_lo(l3.x); c1 += bf_hi(h3.x) + bf_hi(l3.x);
            c2 += bf_lo(h3.y) + bf_lo(l3.y); c3 += bf_hi(h3.y) + bf_hi(l3.y);
        }
        for (; j < end; j++) {
            int s0 = g_esrc[j];
            uint2 h0 = *(const uint2*)(hhi + (size_t)s0 * DIM + lane * 4);
            uint2 l0 = *(const uint2*)(hlo + (size_t)s0 * DIM + lane * 4);
            a0 += bf_lo(h0.x) + bf_lo(l0.x); a1 += bf_hi(h0.x) + bf_hi(l0.x);
            a2 += bf_lo(h0.y) + bf_lo(l0.y); a3 += bf_hi(h0.y) + bf_hi(l0.y);
        }
    }
    float inv = 1.f / fmaxf((float)(end - beg), 1.f);
    a0 = (a0 + c0) * inv; a1 = (a1 + c1) * inv;
    a2 = (a2 + c2) * inv; a3 = (a3 + c3) * inv;
    uint32_t h01, l01, h23, l23;
    split2(a0, a1, h01, l01);
    split2(a2, a3, h23, l23);
    size_t off = (size_t)node * DIM + lane * 4;
    *(uint32_t*)(g_mhi + off) = h01;
    *(uint32_t*)(g_mhi + off + 2) = h23;
    *(uint32_t*)(g_mlo + off) = l01;
    *(uint32_t*)(g_mlo + off + 2) = l23;
}

// ---------------- B prep for ALL layers: W[n][k] -> hi/lo bf16 row-major [NT][256] ----------------

__global__ void prepB_all(const float* __restrict__ ws1, const float* __restrict__ wn1,
                          const float* __restrict__ ws2, const float* __restrict__ wn2,
                          const float* __restrict__ ws3, const float* __restrict__ wn3) {
    int idx = blockIdx.x * blockDim.x + threadIdx.x;
    const float *ws, *wn;
    __nv_bfloat16 *bh, *bl;
    int nout, rel;
    if (idx < 32768)       { rel = idx;          ws = ws1; wn = wn1; bh = g_B1hi; bl = g_B1lo; nout = 128; }
    else if (idx < 65536)  { rel = idx - 32768;  ws = ws2; wn = wn2; bh = g_B2hi; bl = g_B2lo; nout = 128; }
    else if (idx < 81920)  { rel = idx - 65536;  ws = ws3; wn = wn3; bh = g_B3hi; bl = g_B3lo; nout = N_OUT; }
    else return;
    int n = rel / 256, k = rel % 256;
    float v = 0.f;
    if (n < nout) v = (k < 128) ? ws[n * 128 + k] : wn[n * 128 + (k - 128)];
    __nv_bfloat16 h = __float2bfloat16(v);
    __nv_bfloat16 l = __float2bfloat16(v - __bfloat162float(h));
    bh[rel] = h;
    bl[rel] = l;
}

// ---------------- mma.sync split-bf16 GEMM ----------------
// 256 thr = 8 warps (4m x 2n). CTA tile 128 x BN, BK=32. m16n8k16 bf16 HMMA, fp32 accum.
// 3 passes: Ahi*Bhi + Ahi*Blo + Alo*Bhi. Frag loads via ldmatrix.x4; reg prefetch staging.

__device__ __forceinline__ void mma16816(float* c, const uint32_t* a, const uint32_t* b) {
    asm volatile(
        "mma.sync.aligned.m16n8k16.row.col.f32.bf16.bf16.f32 "
        "{%0,%1,%2,%3}, {%4,%5,%6,%7}, {%8,%9}, {%0,%1,%2,%3};"
        : "+f"(c[0]), "+f"(c[1]), "+f"(c[2]), "+f"(c[3])
        : "r"(a[0]), "r"(a[1]), "r"(a[2]), "r"(a[3]), "r"(b[0]), "r"(b[1]));
}

#define BKP 40  // padded row: 32 bf16 + 8 (stride 80B -> conflict-free LDS/LDSM)

template <int BN, int NOUT, bool RELU, bool L1, bool OUTP>
__global__ void __launch_bounds__(256) gemm_mma(
    const float* __restrict__ xf,
    const __nv_bfloat16* __restrict__ Ahi, const __nv_bfloat16* __restrict__ Alo,
    const __nv_bfloat16* __restrict__ Bhi, const __nv_bfloat16* __restrict__ Blo,
    const float* __restrict__ bias,
    float* __restrict__ outf,
    __nv_bfloat16* __restrict__ outHi, __nv_bfloat16* __restrict__ outLo) {
    constexpr int HN = BN / 2;
    constexpr int NF = HN / 8;
    constexpr int BITER = BN / 32;  // B uint2s per thread
    __shared__ __align__(16) uint16_t As_hi[128][BKP];
    __shared__ __align__(16) uint16_t As_lo[128][BKP];
    __shared__ __align__(16) uint16_t Bs_hi[BN][BKP];
    __shared__ __align__(16) uint16_t Bs_lo[BN][BKP];

    int tid = threadIdx.x;
    int warp = tid >> 5, lane = tid & 31;
    int wm = warp & 3, wn = warp >> 2;
    int qrow = lane >> 2, qk2 = (lane & 3) * 2;
    int rowBase = blockIdx.x * 128;

    float c[2][NF][4];
#pragma unroll
    for (int mi = 0; mi < 2; mi++)
#pragma unroll
        for (int ni = 0; ni < NF; ni++)
#pragma unroll
            for (int j = 0; j < 4; j++) c[mi][ni][j] = 0.f;

    int g = lane >> 3, l = lane & 7;
    uint32_t aoff = (uint32_t)(((wm * 32 + ((g & 1) << 3) + l) * BKP + ((g >> 1) << 3)) * 2);
    uint32_t boff = (uint32_t)(((wn * HN + ((g & 2) << 2) + l) * BKP + ((g & 1) << 3)) * 2);
    uint32_t aAddrHi = (uint32_t)__cvta_generic_to_shared(As_hi) + aoff;
    uint32_t aAddrLo = (uint32_t)__cvta_generic_to_shared(As_lo) + aoff;
    uint32_t bAddrHi = (uint32_t)__cvta_generic_to_shared(Bs_hi) + boff;
    uint32_t bAddrLo = (uint32_t)__cvta_generic_to_shared(Bs_lo) + boff;

    uint2 rah[4], ral[4], rbh[BITER], rbl[BITER];

    auto loadA = [&](int kb) {
        if (L1 && kb < 128) {
#pragma unroll
            for (int i = 0; i < 4; i++) {
                int idx = tid + i * 256;
                int r = idx >> 3, u = idx & 7;
                int gr = rowBase + r;
                if (gr >= N_NODES) gr = N_NODES - 1;
                float4 v = *(const float4*)(xf + (size_t)gr * 128 + kb + u * 4);
                split2(v.x, v.y, rah[i].x, ral[i].x);
                split2(v.z, v.w, rah[i].y, ral[i].y);
            }
        } else {
            const __nv_bfloat16* sh = (kb < 128) ? Ahi + kb : g_mhi + (kb - 128);
            const __nv_bfloat16* sl = (kb < 128) ? Alo + kb : g_mlo + (kb - 128);
#pragma unroll
            for (int i = 0; i < 4; i++) {
                int idx = tid + i * 256;
                int r = idx >> 3, u = idx & 7;
                int gr = rowBase + r;
                if (gr >= N_NODES) gr = N_NODES - 1;
                rah[i] = *(const uint2*)(sh + (size_t)gr * 128 + u * 4);
                ral[i] = *(const uint2*)(sl + (size_t)gr * 128 + u * 4);
            }
        }
    };
    auto loadB = [&](int kb) {
#pragma unroll
        for (int i = 0; i < BITER; i++) {
            int idx = tid + i * 256;
            int n = idx >> 3, u = idx & 7;
            rbh[i] = *(const uint2*)(Bhi + n * 256 + kb + u * 4);
            rbl[i] = *(const uint2*)(Blo + n * 256 + kb + u * 4);
        }
    };

    loadA(0);
    loadB(0);

    for (int t = 0; t < 8; t++) {
        int kb = t * 32;
        __syncthreads();
#pragma unroll
        for (int i = 0; i < 4; i++) {
            int idx = tid + i * 256;
            int r = idx >> 3, u = idx & 7;
            *(uint2*)&As_hi[r][u * 4] = rah[i];
            *(uint2*)&As_lo[r][u * 4] = ral[i];
        }
#pragma unroll
        for (int i = 0; i < BITER; i++) {
            int idx = tid + i * 256;
            int n = idx >> 3, u = idx & 7;
            *(uint2*)&Bs_hi[n][u * 4] = rbh[i];
            *(uint2*)&Bs_lo[n][u * 4] = rbl[i];
        }
        __syncthreads();
        if (t < 7) { loadA(kb + 32); loadB(kb + 32); }

#pragma unroll
        for (int kk = 0; kk < 2; kk++) {
            uint32_t koff = kk * 32;
            uint32_t a_hi[2][4], a_lo[2][4];
#pragma unroll
            for (int mi = 0; mi < 2; mi++) {
                ldsm4(a_hi[mi], aAddrHi + mi * (16 * BKP * 2) + koff);
                ldsm4(a_lo[mi], aAddrLo + mi * (16 * BKP * 2) + koff);
            }
#pragma unroll
            for (int nj = 0; nj < NF / 2; nj++) {
                uint32_t bh[4], bl[4];
                ldsm4(bh, bAddrHi + nj * (16 * BKP * 2) + koff);
                ldsm4(bl, bAddrLo + nj * (16 * BKP * 2) + koff);
#pragma unroll
                for (int hh = 0; hh < 2; hh++) {
                    int ni = nj * 2 + hh;
#pragma unroll
                    for (int mi = 0; mi < 2; mi++) {
                        mma16816(c[mi][ni], a_hi[mi], bh + hh * 2);
                        mma16816(c[mi][ni], a_hi[mi], bl + hh * 2);
                        mma16816(c[mi][ni], a_lo[mi], bh + hh * 2);
                    }
                }
            }
        }
    }

    // ---- epilogue ----
#pragma unroll
    for (int mi = 0; mi < 2; mi++) {
        int r0 = rowBase + wm * 32 + mi * 16 + qrow;
#pragma unroll
        for (int ni = 0; ni < NF; ni++) {
            int col = wn * HN + ni * 8 + qk2;
            float b0 = (col < NOUT) ? bias[col] : 0.f;
            float b1 = (col + 1 < NOUT) ? bias[col + 1] : 0.f;
            float v0 = c[mi][ni][0] + b0, v1 = c[mi][ni][1] + b1;
            float v2 = c[mi][ni][2] + b0, v3 = c[mi][ni][3] + b1;
            if (RELU) {
                v0 = fmaxf(v0, 0.f); v1 = fmaxf(v1, 0.f);
                v2 = fmaxf(v2, 0.f); v3 = fmaxf(v3, 0.f);
            }
            if (OUTP) {
                if (r0 < N_NODES) {
                    uint32_t hi, lo;
                    split2(v0, v1, hi, lo);
                    *(uint32_t*)(outHi + (size_t)r0 * 128 + col) = hi;
                    *(uint32_t*)(outLo + (size_t)r0 * 128 + col) = lo;
                }
                if (r0 + 8 < N_NODES) {
                    uint32_t hi, lo;
                    split2(v2, v3, hi, lo);
                    *(uint32_t*)(outHi + (size_t)(r0 + 8) * 128 + col) = hi;
                    *(uint32_t*)(outLo + (size_t)(r0 + 8) * 128 + col) = lo;
                }
            } else {
                if (r0 < N_NODES) {
                    if (col < NOUT)     outf[(size_t)r0 * NOUT + col]     = v0;
                    if (col + 1 < NOUT) outf[(size_t)r0 * NOUT + col + 1] = v1;
                }
                if (r0 + 8 < N_NODES) {
                    if (col < NOUT)     outf[(size_t)(r0 + 8) * NOUT + col]     = v2;
                    if (col + 1 < NOUT) outf[(size_t)(r0 + 8) * NOUT + col + 1] = v3;
                }
            }
        }
    }
}

// ---------------- launch ----------------

extern "C" void kernel_launch(void* const* d_in, const int* in_sizes, int n_in,
                              void* d_out, int out_size) {
    const float* x   = (const float*)d_in[0];
    const int*   src = (const int*)d_in[1];
    const int*   dst = (const int*)d_in[2];
    const float* ws1 = (const float*)d_in[3];
    const float* wn1 = (const float*)d_in[4];
    const float* b1  = (const float*)d_in[5];
    const float* ws2 = (const float*)d_in[6];
    const float* wn2 = (const float*)d_in[7];
    const float* b2  = (const float*)d_in[8];
    const float* ws3 = (const float*)d_in[9];
    const float* wn3 = (const float*)d_in[10];
    const float* b3  = (const float*)d_in[11];
    float* out = (float*)d_out;

    void *p0h, *p0l, *p1h, *p1l, *pcur;
    void *pb1h, *pb1l, *pb2h, *pb2l, *pb3h, *pb3l;
    cudaGetSymbolAddress(&p0h, g_f0hi);
    cudaGetSymbolAddress(&p0l, g_f0lo);
    cudaGetSymbolAddress(&p1h, g_f1hi);
    cudaGetSymbolAddress(&p1l, g_f1lo);
    cudaGetSymbolAddress(&pcur, g_cursor);
    cudaGetSymbolAddress(&pb1h, g_B1hi);
    cudaGetSymbolAddress(&pb1l, g_B1lo);
    cudaGetSymbolAddress(&pb2h, g_B2hi);
    cudaGetSymbolAddress(&pb2l, g_B2lo);
    cudaGetSymbolAddress(&pb3h, g_B3hi);
    cudaGetSymbolAddress(&pb3l, g_B3lo);
    __nv_bfloat16* f0hi = (__nv_bfloat16*)p0h;
    __nv_bfloat16* f0lo = (__nv_bfloat16*)p0l;
    __nv_bfloat16* f1hi = (__nv_bfloat16*)p1h;
    __nv_bfloat16* f1lo = (__nv_bfloat16*)p1l;

    const int EB = (N_EDGES + 255) / 256;
    const int AGG_B = (N_NODES * 32 + 255) / 256;
    const int GEMM_B = (N_NODES + 127) / 128;

    // CSR build (cursor zeroed via async memset — capture-legal)
    cudaMemsetAsync(pcur, 0, N_NODES * sizeof(int));
    count_k<<<EB, 256>>>(dst);
    scan_k<<<1, 1024>>>();
    bucket_k<<<EB, 256>>>(src, dst);

    // Layer 1: A self = x (fp32), mean from fp32 gather; out packed
    agg_k<true><<<AGG_B, 256>>>(x, nullptr, nullptr);
    prepB_all<<<(81920 + 255) / 256, 256>>>(ws1, wn1, ws2, wn2, ws3, wn3);
    gemm_mma<128, 128, true, true, true><<<GEMM_B, 256>>>(
        x, nullptr, nullptr, (const __nv_bfloat16*)pb1h, (const __nv_bfloat16*)pb1l,
        b1, nullptr, f0hi, f0lo);

    // Layer 2: packed A, packed gather; out packed
    agg_k<false><<<AGG_B, 256>>>(nullptr, f0hi, f0lo);
    gemm_mma<128, 128, true, false, true><<<GEMM_B, 256>>>(
        nullptr, f0hi, f0lo, (const __nv_bfloat16*)pb2h, (const __nv_bfloat16*)pb2l,
        b2, nullptr, f1hi, f1lo);

    // Layer 3: packed A, packed gather; fp32 out
    agg_k<false><<<AGG_B, 256>>>(nullptr, f1hi, f1lo);
    gemm_mma<64, N_OUT, false, false, false><<<GEMM_B, 256>>>(
        nullptr, f1hi, f1lo, (const __nv_bfloat16*)pb3h, (const __nv_bfloat16*)pb3l,
        b3, out, nullptr, nullptr);
}

// round 16
// speedup vs baseline: 1.1908x; 1.0826x over previous
#include <cuda_runtime.h>
#include <cuda_bf16.h>
#include <cstdint>

#define N_NODES 50000
#define DIM 128
#define N_EDGES 800000
#define N_OUT 47

// ---------------- scratch (device globals; no allocation allowed) ----------------
// feature rows: 128 elems stored interleaved as 64 x uint2 {h01, l01}:
//   uint32[row*128 + e]   = pack(hi(e), hi(e+1))   (e even)
//   uint32[row*128 + e+1] = pack(lo(e), lo(e+1))
__device__ __align__(16) uint32_t g_f0[N_NODES * DIM];
__device__ __align__(16) uint32_t g_f1[N_NODES * DIM];
__device__ __align__(16) uint32_t g_m [N_NODES * DIM];
__device__ int   g_rowptr[N_NODES + 1];
__device__ __align__(16) int g_cursor[N_NODES];
__device__ int   g_esrc[N_EDGES];
__device__ __align__(16) __nv_bfloat16 g_B1hi[128 * 256];
__device__ __align__(16) __nv_bfloat16 g_B1lo[128 * 256];
__device__ __align__(16) __nv_bfloat16 g_B2hi[128 * 256];
__device__ __align__(16) __nv_bfloat16 g_B2lo[128 * 256];
__device__ __align__(16) __nv_bfloat16 g_B3hi[64 * 256];
__device__ __align__(16) __nv_bfloat16 g_B3lo[64 * 256];

// ---------------- helpers ----------------

__device__ __forceinline__ uint32_t pack_bf16(__nv_bfloat16 l, __nv_bfloat16 h) {
    return ((uint32_t)__bfloat16_as_ushort(h) << 16) | __bfloat16_as_ushort(l);
}
__device__ __forceinline__ float bf_lo(uint32_t w) { return __uint_as_float(w << 16); }
__device__ __forceinline__ float bf_hi(uint32_t w) { return __uint_as_float(w & 0xFFFF0000u); }

__device__ __forceinline__ void split2(float v0, float v1, uint32_t& hi, uint32_t& lo) {
    __nv_bfloat16 h0 = __float2bfloat16(v0), h1 = __float2bfloat16(v1);
    __nv_bfloat16 l0 = __float2bfloat16(v0 - __bfloat162float(h0));
    __nv_bfloat16 l1 = __float2bfloat16(v1 - __bfloat162float(h1));
    hi = pack_bf16(h0, h1);
    lo = pack_bf16(l0, l1);
}

__device__ __forceinline__ void ldsm4(uint32_t* r, uint32_t addr) {
    asm volatile("ldmatrix.sync.aligned.m8n8.x4.shared.b16 {%0,%1,%2,%3}, [%4];"
        : "=r"(r[0]), "=r"(r[1]), "=r"(r[2]), "=r"(r[3]) : "r"(addr));
}

// ---------------- CSR build (by dst) ----------------

__global__ void count_k(const int* __restrict__ dst) {
    int e = blockIdx.x * blockDim.x + threadIdx.x;
    if (e < N_EDGES) atomicAdd(&g_cursor[dst[e]], 1);
}
__global__ void scan_k() {
    __shared__ int ssum[1024];
    int t = threadIdx.x;
    const int CH = (N_NODES + 1023) / 1024;
    int base = t * CH;
    int s = 0;
    for (int i = 0; i < CH; i++) { int idx = base + i; if (idx < N_NODES) s += g_cursor[idx]; }
    ssum[t] = s;
    __syncthreads();
    for (int off = 1; off < 1024; off <<= 1) {
        int v = 0;
        if (t >= off) v = ssum[t - off];
        __syncthreads();
        if (t >= off) ssum[t] += v;
        __syncthreads();
    }
    int run = (t == 0) ? 0 : ssum[t - 1];
    for (int i = 0; i < CH; i++) {
        int idx = base + i;
        if (idx < N_NODES) {
            int c = g_cursor[idx];
            g_rowptr[idx] = run;
            g_cursor[idx] = run;
            run += c;
        }
    }
    if (t == 0) g_rowptr[N_NODES] = N_EDGES;
}
__global__ void bucket_k(const int* __restrict__ src, const int* __restrict__ dst) {
    int e = blockIdx.x * blockDim.x + threadIdx.x;
    if (e < N_EDGES) {
        int pos = atomicAdd(&g_cursor[dst[e]], 1);
        g_esrc[pos] = src[e];
    }
}

// ---------------- mean aggregation: one warp per node, 4-edge unroll ----------------
// GF32: gather fp32 x; else gather interleaved packed rows. Writes interleaved mean.

template <bool GF32>
__global__ void agg_k(const float* __restrict__ xf, const uint32_t* __restrict__ h32) {
    int gt = blockIdx.x * blockDim.x + threadIdx.x;
    int node = gt >> 5, lane = gt & 31;
    if (node >= N_NODES) return;
    int beg = g_rowptr[node], end = g_rowptr[node + 1];
    float a0 = 0.f, a1 = 0.f, a2 = 0.f, a3 = 0.f;
    float c0 = 0.f, c1 = 0.f, c2 = 0.f, c3 = 0.f;
    int j = beg;
    if (GF32) {
        for (; j + 3 < end; j += 4) {
            int s0 = g_esrc[j], s1 = g_esrc[j + 1], s2 = g_esrc[j + 2], s3 = g_esrc[j + 3];
            float4 v0 = *(const float4*)(xf + (size_t)s0 * DIM + lane * 4);
            float4 v1 = *(const float4*)(xf + (size_t)s1 * DIM + lane * 4);
            float4 v2 = *(const float4*)(xf + (size_t)s2 * DIM + lane * 4);
            float4 v3 = *(const float4*)(xf + (size_t)s3 * DIM + lane * 4);
            a0 += v0.x; a1 += v0.y; a2 += v0.z; a3 += v0.w;
            c0 += v1.x; c1 += v1.y; c2 += v1.z; c3 += v1.w;
            a0 += v2.x; a1 += v2.y; a2 += v2.z; a3 += v2.w;
            c0 += v3.x; c1 += v3.y; c2 += v3.z; c3 += v3.w;
        }
        for (; j < end; j++) {
            int s0 = g_esrc[j];
            float4 v0 = *(const float4*)(xf + (size_t)s0 * DIM + lane * 4);
            a0 += v0.x; a1 += v0.y; a2 += v0.z; a3 += v0.w;
        }
    } else {
        // per edge: ONE uint4 = {h01, l01, h23, l23} covering elems 4*lane .. 4*lane+3
        for (; j + 3 < end; j += 4) {
            int s0 = g_esrc[j], s1 = g_esrc[j + 1], s2 = g_esrc[j + 2], s3 = g_esrc[j + 3];
            uint4 v0 = *(const uint4*)(h32 + (size_t)s0 * DIM + lane * 4);
            uint4 v1 = *(const uint4*)(h32 + (size_t)s1 * DIM + lane * 4);
            uint4 v2 = *(const uint4*)(h32 + (size_t)s2 * DIM + lane * 4);
            uint4 v3 = *(const uint4*)(h32 + (size_t)s3 * DIM + lane * 4);
            a0 += bf_lo(v0.x) + bf_lo(v0.y); a1 += bf_hi(v0.x) + bf_hi(v0.y);
            a2 += bf_lo(v0.z) + bf_lo(v0.w); a3 += bf_hi(v0.z) + bf_hi(v0.w);
            c0 += bf_lo(v1.x) + bf_lo(v1.y); c1 += bf_hi(v1.x) + bf_hi(v1.y);
            c2 += bf_lo(v1.z) + bf_lo(v1.w); c3 += bf_hi(v1.z) + bf_hi(v1.w);
            a0 += bf_lo(v2.x) + bf_lo(v2.y); a1 += bf_hi(v2.x) + bf_hi(v2.y);
            a2 += bf_lo(v2.z) + bf_lo(v2.w); a3 += bf_hi(v2.z) + bf_hi(v2.w);
            c0 += bf_lo(v3.x) + bf_lo(v3.y); c1 += bf_hi(v3.x) + bf_hi(v3.y);
            c2 += bf_lo(v3.z) + bf_lo(v3.w); c3 += bf_hi(v3.z) + bf_hi(v3.w);
        }
        for (; j < end; j++) {
            int s0 = g_esrc[j];
            uint4 v0 = *(const uint4*)(h32 + (size_t)s0 * DIM + lane * 4);
            a0 += bf_lo(v0.x) + bf_lo(v0.y); a1 += bf_hi(v0.x) + bf_hi(v0.y);
            a2 += bf_lo(v0.z) + bf_lo(v0.w); a3 += bf_hi(v0.z) + bf_hi(v0.w);
        }
    }
    float inv = 1.f / fmaxf((float)(end - beg), 1.f);
    a0 = (a0 + c0) * inv; a1 = (a1 + c1) * inv;
    a2 = (a2 + c2) * inv; a3 = (a3 + c3) * inv;
    uint32_t h01, l01, h23, l23;
    split2(a0, a1, h01, l01);
    split2(a2, a3, h23, l23);
    *(uint4*)(g_m + (size_t)node * DIM + lane * 4) = make_uint4(h01, l01, h23, l23);
}

// ---------------- B prep for ALL layers: W[n][k] -> hi/lo bf16 row-major [NT][256] ----------------

__global__ void prepB_all(const float* __restrict__ ws1, const float* __restrict__ wn1,
                          const float* __restrict__ ws2, const float* __restrict__ wn2,
                          const float* __restrict__ ws3, const float* __restrict__ wn3) {
    int idx = blockIdx.x * blockDim.x + threadIdx.x;
    const float *ws, *wn;
    __nv_bfloat16 *bh, *bl;
    int nout, rel;
    if (idx < 32768)       { rel = idx;          ws = ws1; wn = wn1; bh = g_B1hi; bl = g_B1lo; nout = 128; }
    else if (idx < 65536)  { rel = idx - 32768;  ws = ws2; wn = wn2; bh = g_B2hi; bl = g_B2lo; nout = 128; }
    else if (idx < 81920)  { rel = idx - 65536;  ws = ws3; wn = wn3; bh = g_B3hi; bl = g_B3lo; nout = N_OUT; }
    else return;
    int n = rel / 256, k = rel % 256;
    float v = 0.f;
    if (n < nout) v = (k < 128) ? ws[n * 128 + k] : wn[n * 128 + (k - 128)];
    __nv_bfloat16 h = __float2bfloat16(v);
    __nv_bfloat16 l = __float2bfloat16(v - __bfloat162float(h));
    bh[rel] = h;
    bl[rel] = l;
}

// ---------------- mma.sync split-bf16 GEMM ----------------
// 256 thr = 8 warps (4m x 2n). CTA tile 128 x BN, BK=32. m16n8k16 bf16 HMMA, fp32 accum.
// 3 passes: Ahi*Bhi + Ahi*Blo + Alo*Bhi. ldmatrix frag loads; reg prefetch staging.

__device__ __forceinline__ void mma16816(float* c, const uint32_t* a, const uint32_t* b) {
    asm volatile(
        "mma.sync.aligned.m16n8k16.row.col.f32.bf16.bf16.f32 "
        "{%0,%1,%2,%3}, {%4,%5,%6,%7}, {%8,%9}, {%0,%1,%2,%3};"
        : "+f"(c[0]), "+f"(c[1]), "+f"(c[2]), "+f"(c[3])
        : "r"(a[0]), "r"(a[1]), "r"(a[2]), "r"(a[3]), "r"(b[0]), "r"(b[1]));
}

#define BKP 40  // padded row: 32 bf16 + 8 (stride 80B -> conflict-free LDS/LDSM)

template <int BN, int NOUT, bool RELU, bool L1, bool OUTP>
__global__ void __launch_bounds__(256) gemm_mma(
    const float* __restrict__ xf,
    const uint32_t* __restrict__ A32,
    const __nv_bfloat16* __restrict__ Bhi, const __nv_bfloat16* __restrict__ Blo,
    const float* __restrict__ bias,
    float* __restrict__ outf,
    uint32_t* __restrict__ out32) {
    constexpr int HN = BN / 2;
    constexpr int NF = HN / 8;
    constexpr int BITER = BN / 32;
    __shared__ __align__(16) uint16_t As_hi[128][BKP];
    __shared__ __align__(16) uint16_t As_lo[128][BKP];
    __shared__ __align__(16) uint16_t Bs_hi[BN][BKP];
    __shared__ __align__(16) uint16_t Bs_lo[BN][BKP];

    int tid = threadIdx.x;
    int warp = tid >> 5, lane = tid & 31;
    int wm = warp & 3, wn = warp >> 2;
    int qrow = lane >> 2, qk2 = (lane & 3) * 2;
    int rowBase = blockIdx.x * 128;

    float c[2][NF][4];
#pragma unroll
    for (int mi = 0; mi < 2; mi++)
#pragma unroll
        for (int ni = 0; ni < NF; ni++)
#pragma unroll
            for (int j = 0; j < 4; j++) c[mi][ni][j] = 0.f;

    int g = lane >> 3, l = lane & 7;
    uint32_t aoff = (uint32_t)(((wm * 32 + ((g & 1) << 3) + l) * BKP + ((g >> 1) << 3)) * 2);
    uint32_t boff = (uint32_t)(((wn * HN + ((g & 2) << 2) + l) * BKP + ((g & 1) << 3)) * 2);
    uint32_t aAddrHi = (uint32_t)__cvta_generic_to_shared(As_hi) + aoff;
    uint32_t aAddrLo = (uint32_t)__cvta_generic_to_shared(As_lo) + aoff;
    uint32_t bAddrHi = (uint32_t)__cvta_generic_to_shared(Bs_hi) + boff;
    uint32_t bAddrLo = (uint32_t)__cvta_generic_to_shared(Bs_lo) + boff;

    uint2 rah[4], ral[4], rbh[BITER], rbl[BITER];

    auto loadA = [&](int kb) {
        if (L1 && kb < 128) {
#pragma unroll
            for (int i = 0; i < 4; i++) {
                int idx = tid + i * 256;
                int r = idx >> 3, u = idx & 7;
                int gr = rowBase + r;
                if (gr >= N_NODES) gr = N_NODES - 1;
                float4 v = *(const float4*)(xf + (size_t)gr * 128 + kb + u * 4);
                split2(v.x, v.y, rah[i].x, ral[i].x);
                split2(v.z, v.w, rah[i].y, ral[i].y);
            }
        } else {
            const uint32_t* s = (kb < 128) ? A32 + kb : g_m + (kb - 128);
#pragma unroll
            for (int i = 0; i < 4; i++) {
                int idx = tid + i * 256;
                int r = idx >> 3, u = idx & 7;
                int gr = rowBase + r;
                if (gr >= N_NODES) gr = N_NODES - 1;
                uint4 v = *(const uint4*)(s + (size_t)gr * 128 + u * 4);
                rah[i] = make_uint2(v.x, v.z);
                ral[i] = make_uint2(v.y, v.w);
            }
        }
    };
    auto loadB = [&](int kb) {
#pragma unroll
        for (int i = 0; i < BITER; i++) {
            int idx = tid + i * 256;
            int n = idx >> 3, u = idx & 7;
            rbh[i] = *(const uint2*)(Bhi + n * 256 + kb + u * 4);
            rbl[i] = *(const uint2*)(Blo + n * 256 + kb + u * 4);
        }
    };

    loadA(0);
    loadB(0);

    for (int t = 0; t < 8; t++) {
        int kb = t * 32;
        __syncthreads();
#pragma unroll
        for (int i = 0; i < 4; i++) {
            int idx = tid + i * 256;
            int r = idx >> 3, u = idx & 7;
            *(uint2*)&As_hi[r][u * 4] = rah[i];
            *(uint2*)&As_lo[r][u * 4] = ral[i];
        }
#pragma unroll
        for (int i = 0; i < BITER; i++) {
            int idx = tid + i * 256;
            int n = idx >> 3, u = idx & 7;
            *(uint2*)&Bs_hi[n][u * 4] = rbh[i];
            *(uint2*)&Bs_lo[n][u * 4] = rbl[i];
        }
        __syncthreads();
        if (t < 7) { loadA(kb + 32); loadB(kb + 32); }

#pragma unroll
        for (int kk = 0; kk < 2; kk++) {
            uint32_t koff = kk * 32;
            uint32_t a_hi[2][4], a_lo[2][4];
#pragma unroll
            for (int mi = 0; mi < 2; mi++) {
                ldsm4(a_hi[mi], aAddrHi + mi * (16 * BKP * 2) + koff);
                ldsm4(a_lo[mi], aAddrLo + mi * (16 * BKP * 2) + koff);
            }
#pragma unroll
            for (int nj = 0; nj < NF / 2; nj++) {
                uint32_t bh[4], bl[4];
                ldsm4(bh, bAddrHi + nj * (16 * BKP * 2) + koff);
                ldsm4(bl, bAddrLo + nj * (16 * BKP * 2) + koff);
#pragma unroll
                for (int hh = 0; hh < 2; hh++) {
                    int ni = nj * 2 + hh;
#pragma unroll
                    for (int mi = 0; mi < 2; mi++) {
                        mma16816(c[mi][ni], a_hi[mi], bh + hh * 2);
                        mma16816(c[mi][ni], a_hi[mi], bl + hh * 2);
                        mma16816(c[mi][ni], a_lo[mi], bh + hh * 2);
                    }
                }
            }
        }
    }

    // ---- epilogue ----
#pragma unroll
    for (int mi = 0; mi < 2; mi++) {
        int r0 = rowBase + wm * 32 + mi * 16 + qrow;
#pragma unroll
        for (int ni = 0; ni < NF; ni++) {
            int col = wn * HN + ni * 8 + qk2;   // even
            float b0 = (col < NOUT) ? bias[col] : 0.f;
            float b1 = (col + 1 < NOUT) ? bias[col + 1] : 0.f;
            float v0 = c[mi][ni][0] + b0, v1 = c[mi][ni][1] + b1;
            float v2 = c[mi][ni][2] + b0, v3 = c[mi][ni][3] + b1;
            if (RELU) {
                v0 = fmaxf(v0, 0.f); v1 = fmaxf(v1, 0.f);
                v2 = fmaxf(v2, 0.f); v3 = fmaxf(v3, 0.f);
            }
            if (OUTP) {
                if (r0 < N_NODES) {
                    uint32_t hi, lo;
                    split2(v0, v1, hi, lo);
                    *(uint2*)(out32 + (size_t)r0 * 128 + col) = make_uint2(hi, lo);
                }
                if (r0 + 8 < N_NODES) {
                    uint32_t hi, lo;
                    split2(v2, v3, hi, lo);
                    *(uint2*)(out32 + (size_t)(r0 + 8) * 128 + col) = make_uint2(hi, lo);
                }
            } else {
                if (r0 < N_NODES) {
                    if (col < NOUT)     outf[(size_t)r0 * NOUT + col]     = v0;
                    if (col + 1 < NOUT) outf[(size_t)r0 * NOUT + col + 1] = v1;
                }
                if (r0 + 8 < N_NODES) {
                    if (col < NOUT)     outf[(size_t)(r0 + 8) * NOUT + col]     = v2;
                    if (col + 1 < NOUT) outf[(size_t)(r0 + 8) * NOUT + col + 1] = v3;
                }
            }
        }
    }
}

// ---------------- launch ----------------

extern "C" void kernel_launch(void* const* d_in, const int* in_sizes, int n_in,
                              void* d_out, int out_size) {
    const float* x   = (const float*)d_in[0];
    const int*   src = (const int*)d_in[1];
    const int*   dst = (const int*)d_in[2];
    const float* ws1 = (const float*)d_in[3];
    const float* wn1 = (const float*)d_in[4];
    const float* b1  = (const float*)d_in[5];
    const float* ws2 = (const float*)d_in[6];
    const float* wn2 = (const float*)d_in[7];
    const float* b2  = (const float*)d_in[8];
    const float* ws3 = (const float*)d_in[9];
    const float* wn3 = (const float*)d_in[10];
    const float* b3  = (const float*)d_in[11];
    float* out = (float*)d_out;

    void *pf0, *pf1, *pcur;
    void *pb1h, *pb1l, *pb2h, *pb2l, *pb3h, *pb3l;
    cudaGetSymbolAddress(&pf0, g_f0);
    cudaGetSymbolAddress(&pf1, g_f1);
    cudaGetSymbolAddress(&pcur, g_cursor);
    cudaGetSymbolAddress(&pb1h, g_B1hi);
    cudaGetSymbolAddress(&pb1l, g_B1lo);
    cudaGetSymbolAddress(&pb2h, g_B2hi);
    cudaGetSymbolAddress(&pb2l, g_B2lo);
    cudaGetSymbolAddress(&pb3h, g_B3hi);
    cudaGetSymbolAddress(&pb3l, g_B3lo);
    uint32_t* f0 = (uint32_t*)pf0;
    uint32_t* f1 = (uint32_t*)pf1;

    const int EB = (N_EDGES + 255) / 256;
    const int AGG_B = (N_NODES * 32 + 255) / 256;
    const int GEMM_B = (N_NODES + 127) / 128;

    // CSR build (cursor zeroed via async memset — capture-legal)
    cudaMemsetAsync(pcur, 0, N_NODES * sizeof(int));
    count_k<<<EB, 256>>>(dst);
    scan_k<<<1, 1024>>>();
    bucket_k<<<EB, 256>>>(src, dst);

    // Layer 1: A self = x (fp32), mean from fp32 gather; out interleaved packed
    agg_k<true><<<AGG_B, 256>>>(x, nullptr);
    prepB_all<<<(81920 + 255) / 256, 256>>>(ws1, wn1, ws2, wn2, ws3, wn3);
    gemm_mma<128, 128, true, true, true><<<GEMM_B, 256>>>(
        x, nullptr, (const __nv_bfloat16*)pb1h, (const __nv_bfloat16*)pb1l,
        b1, nullptr, f0);

    // Layer 2: interleaved A + gather; out interleaved
    agg_k<false><<<AGG_B, 256>>>(nullptr, f0);
    gemm_mma<128, 128, true, false, true><<<GEMM_B, 256>>>(
        nullptr, f0, (const __nv_bfloat16*)pb2h, (const __nv_bfloat16*)pb2l,
        b2, nullptr, f1);

    // Layer 3: interleaved A + gather; fp32 out
    agg_k<false><<<AGG_B, 256>>>(nullptr, f1);
    gemm_mma<64, N_OUT, false, false, false><<<GEMM_B, 256>>>(
        nullptr, f1, (const __nv_bfloat16*)pb3h, (const __nv_bfloat16*)pb3l,
        b3, out, nullptr);
}

// round 17
// speedup vs baseline: 1.4495x; 1.2173x over previous
#include <cuda_runtime.h>
#include <cuda_fp16.h>
#include <cstdint>

#define N_NODES 50000
#define DIM 128
#define N_EDGES 800000
#define N_OUT 47

// ---------------- scratch (device globals; no allocation allowed) ----------------
// feature rows: 128 fp16 elems = 64 uint32 (half2 pairs), 256 B/row
__device__ __align__(16) uint32_t g_x16[N_NODES * 64];
__device__ __align__(16) uint32_t g_f0 [N_NODES * 64];
__device__ __align__(16) uint32_t g_f1 [N_NODES * 64];
__device__ __align__(16) uint32_t g_m  [N_NODES * 64];
__device__ int   g_rowptr[N_NODES + 1];
__device__ __align__(16) int g_cursor[N_NODES];
__device__ int   g_esrc[N_EDGES];
// weights: split fp16 (hi = fp16(w), lo = fp16(w - hi)), row-major [NT][256]
__device__ __align__(16) __half g_B1hi[128 * 256];
__device__ __align__(16) __half g_B1lo[128 * 256];
__device__ __align__(16) __half g_B2hi[128 * 256];
__device__ __align__(16) __half g_B2lo[128 * 256];
__device__ __align__(16) __half g_B3hi[64 * 256];
__device__ __align__(16) __half g_B3lo[64 * 256];

// ---------------- helpers ----------------

__device__ __forceinline__ uint32_t pack_h2(float a, float b) {
    __half2 h = __floats2half2_rn(a, b);
    return *reinterpret_cast<uint32_t*>(&h);
}
__device__ __forceinline__ float2 unpack_h2(uint32_t w) {
    return __half22float2(*reinterpret_cast<const __half2*>(&w));
}
__device__ __forceinline__ void ldsm4(uint32_t* r, uint32_t addr) {
    asm volatile("ldmatrix.sync.aligned.m8n8.x4.shared.b16 {%0,%1,%2,%3}, [%4];"
        : "=r"(r[0]), "=r"(r[1]), "=r"(r[2]), "=r"(r[3]) : "r"(addr));
}

// ---------------- CSR build (by dst); count fused with x->fp16 convert ----------------

__global__ void count_cvt_k(const int* __restrict__ dst, const float* __restrict__ x) {
    int t = blockIdx.x * blockDim.x + threadIdx.x;
    if (t < N_EDGES) atomicAdd(&g_cursor[dst[t]], 1);
    // N_NODES*DIM/8 == 800000 == N_EDGES: each thread converts 8 elems
    if (t < N_NODES * DIM / 8) {
        float4 v0 = *(const float4*)(x + (size_t)t * 8);
        float4 v1 = *(const float4*)(x + (size_t)t * 8 + 4);
        uint4 o;
        o.x = pack_h2(v0.x, v0.y);
        o.y = pack_h2(v0.z, v0.w);
        o.z = pack_h2(v1.x, v1.y);
        o.w = pack_h2(v1.z, v1.w);
        *(uint4*)(g_x16 + (size_t)t * 4) = o;
    }
}
__global__ void scan_k() {
    __shared__ int ssum[1024];
    int t = threadIdx.x;
    const int CH = (N_NODES + 1023) / 1024;
    int base = t * CH;
    int s = 0;
    for (int i = 0; i < CH; i++) { int idx = base + i; if (idx < N_NODES) s += g_cursor[idx]; }
    ssum[t] = s;
    __syncthreads();
    for (int off = 1; off < 1024; off <<= 1) {
        int v = 0;
        if (t >= off) v = ssum[t - off];
        __syncthreads();
        if (t >= off) ssum[t] += v;
        __syncthreads();
    }
    int run = (t == 0) ? 0 : ssum[t - 1];
    for (int i = 0; i < CH; i++) {
        int idx = base + i;
        if (idx < N_NODES) {
            int c = g_cursor[idx];
            g_rowptr[idx] = run;
            g_cursor[idx] = run;
            run += c;
        }
    }
    if (t == 0) g_rowptr[N_NODES] = N_EDGES;
}
__global__ void bucket_k(const int* __restrict__ src, const int* __restrict__ dst) {
    int e = blockIdx.x * blockDim.x + threadIdx.x;
    if (e < N_EDGES) {
        int pos = atomicAdd(&g_cursor[dst[e]], 1);
        g_esrc[pos] = src[e];
    }
}

// ---------------- mean aggregation: one warp per node, 4-edge unroll, fp16 gather ----------------

__global__ void agg_k(const uint32_t* __restrict__ h16) {
    int gt = blockIdx.x * blockDim.x + threadIdx.x;
    int node = gt >> 5, lane = gt & 31;
    if (node >= N_NODES) return;
    int beg = g_rowptr[node], end = g_rowptr[node + 1];
    float a0 = 0.f, a1 = 0.f, a2 = 0.f, a3 = 0.f;
    float c0 = 0.f, c1 = 0.f, c2 = 0.f, c3 = 0.f;
    int j = beg;
    for (; j + 3 < end; j += 4) {
        int s0 = g_esrc[j], s1 = g_esrc[j + 1], s2 = g_esrc[j + 2], s3 = g_esrc[j + 3];
        uint2 v0 = *(const uint2*)(h16 + (size_t)s0 * 64 + lane * 2);
        uint2 v1 = *(const uint2*)(h16 + (size_t)s1 * 64 + lane * 2);
        uint2 v2 = *(const uint2*)(h16 + (size_t)s2 * 64 + lane * 2);
        uint2 v3 = *(const uint2*)(h16 + (size_t)s3 * 64 + lane * 2);
        float2 p;
        p = unpack_h2(v0.x); a0 += p.x; a1 += p.y;
        p = unpack_h2(v0.y); a2 += p.x; a3 += p.y;
        p = unpack_h2(v1.x); c0 += p.x; c1 += p.y;
        p = unpack_h2(v1.y); c2 += p.x; c3 += p.y;
        p = unpack_h2(v2.x); a0 += p.x; a1 += p.y;
        p = unpack_h2(v2.y); a2 += p.x; a3 += p.y;
        p = unpack_h2(v3.x); c0 += p.x; c1 += p.y;
        p = unpack_h2(v3.y); c2 += p.x; c3 += p.y;
    }
    for (; j < end; j++) {
        int s0 = g_esrc[j];
        uint2 v0 = *(const uint2*)(h16 + (size_t)s0 * 64 + lane * 2);
        float2 p;
        p = unpack_h2(v0.x); a0 += p.x; a1 += p.y;
        p = unpack_h2(v0.y); a2 += p.x; a3 += p.y;
    }
    float inv = 1.f / fmaxf((float)(end - beg), 1.f);
    a0 = (a0 + c0) * inv; a1 = (a1 + c1) * inv;
    a2 = (a2 + c2) * inv; a3 = (a3 + c3) * inv;
    *(uint2*)(g_m + (size_t)node * 64 + lane * 2) = make_uint2(pack_h2(a0, a1), pack_h2(a2, a3));
}

// ---------------- B prep for ALL layers: W[n][k] -> hi/lo fp16 row-major [NT][256] ----------------

__global__ void prepB_all(const float* __restrict__ ws1, const float* __restrict__ wn1,
                          const float* __restrict__ ws2, const float* __restrict__ wn2,
                          const float* __restrict__ ws3, const float* __restrict__ wn3) {
    int idx = blockIdx.x * blockDim.x + threadIdx.x;
    const float *ws, *wn;
    __half *bh, *bl;
    int nout, rel;
    if (idx < 32768)       { rel = idx;          ws = ws1; wn = wn1; bh = g_B1hi; bl = g_B1lo; nout = 128; }
    else if (idx < 65536)  { rel = idx - 32768;  ws = ws2; wn = wn2; bh = g_B2hi; bl = g_B2lo; nout = 128; }
    else if (idx < 81920)  { rel = idx - 65536;  ws = ws3; wn = wn3; bh = g_B3hi; bl = g_B3lo; nout = N_OUT; }
    else return;
    int n = rel / 256, k = rel % 256;
    float v = 0.f;
    if (n < nout) v = (k < 128) ? ws[n * 128 + k] : wn[n * 128 + (k - 128)];
    __half h = __float2half_rn(v);
    __half l = __float2half_rn(v - __half2float(h));
    bh[rel] = h;
    bl[rel] = l;
}

// ---------------- mma.sync fp16 GEMM: out = relu?([h|mean] @ W^T + b) ----------------
// 256 thr = 8 warps (4m x 2n). CTA tile 128 x BN, BK=32. m16n8k16 fp16 HMMA, fp32 accum.
// 2 passes: A*Bhi + A*Blo (A = stored fp16 features, exact; B split fp16 = 22-bit weights).

__device__ __forceinline__ void mma16816(float* c, const uint32_t* a, const uint32_t* b) {
    asm volatile(
        "mma.sync.aligned.m16n8k16.row.col.f32.f16.f16.f32 "
        "{%0,%1,%2,%3}, {%4,%5,%6,%7}, {%8,%9}, {%0,%1,%2,%3};"
        : "+f"(c[0]), "+f"(c[1]), "+f"(c[2]), "+f"(c[3])
        : "r"(a[0]), "r"(a[1]), "r"(a[2]), "r"(a[3]), "r"(b[0]), "r"(b[1]));
}

#define BKP 40  // padded row: 32 fp16 + 8 (stride 80B -> conflict-free LDS/LDSM)

template <int BN, int NOUT, bool RELU, bool OUTP>
__global__ void __launch_bounds__(256) gemm_mma(
    const uint32_t* __restrict__ A16,
    const uint32_t* __restrict__ Bhi32, const uint32_t* __restrict__ Blo32,
    const float* __restrict__ bias,
    float* __restrict__ outf,
    uint32_t* __restrict__ out16) {
    constexpr int HN = BN / 2;
    constexpr int NF = HN / 8;
    constexpr int BITER = BN / 64;  // uint4s per thread for one B array
    __shared__ __align__(16) uint16_t As[128][BKP];
    __shared__ __align__(16) uint16_t Bs_hi[BN][BKP];
    __shared__ __align__(16) uint16_t Bs_lo[BN][BKP];

    int tid = threadIdx.x;
    int warp = tid >> 5, lane = tid & 31;
    int wm = warp & 3, wn = warp >> 2;
    int qrow = lane >> 2, qk2 = (lane & 3) * 2;
    int rowBase = blockIdx.x * 128;

    float c[2][NF][4];
#pragma unroll
    for (int mi = 0; mi < 2; mi++)
#pragma unroll
        for (int ni = 0; ni < NF; ni++)
#pragma unroll
            for (int j = 0; j < 4; j++) c[mi][ni][j] = 0.f;

    int g = lane >> 3, l = lane & 7;
    uint32_t aoff = (uint32_t)(((wm * 32 + ((g & 1) << 3) + l) * BKP + ((g >> 1) << 3)) * 2);
    uint32_t boff = (uint32_t)(((wn * HN + ((g & 2) << 2) + l) * BKP + ((g & 1) << 3)) * 2);
    uint32_t aAddr   = (uint32_t)__cvta_generic_to_shared(As) + aoff;
    uint32_t bAddrHi = (uint32_t)__cvta_generic_to_shared(Bs_hi) + boff;
    uint32_t bAddrLo = (uint32_t)__cvta_generic_to_shared(Bs_lo) + boff;

    uint4 ra[2], rbh[BITER], rbl[BITER];

    auto loadA = [&](int kb) {
        const uint32_t* s = (kb < 128) ? A16 + (kb >> 1) : g_m + ((kb - 128) >> 1);
#pragma unroll
        for (int i = 0; i < 2; i++) {
            int idx = tid + i * 256;        // 512 uint4s = 128 rows x 4
            int r = idx >> 2, u = idx & 3;
            int gr = rowBase + r;
            if (gr >= N_NODES) gr = N_NODES - 1;
            ra[i] = *(const uint4*)(s + (size_t)gr * 64 + u * 4);
        }
    };
    auto loadB = [&](int kb) {
#pragma unroll
        for (int i = 0; i < BITER; i++) {
            int idx = tid + i * 256;
            int n = idx >> 2, u = idx & 3;
            rbh[i] = *(const uint4*)(Bhi32 + n * 128 + (kb >> 1) + u * 4);
            rbl[i] = *(const uint4*)(Blo32 + n * 128 + (kb >> 1) + u * 4);
        }
    };

    loadA(0);
    loadB(0);

    for (int t = 0; t < 8; t++) {
        int kb = t * 32;
        __syncthreads();
#pragma unroll
        for (int i = 0; i < 2; i++) {
            int idx = tid + i * 256;
            int r = idx >> 2, u = idx & 3;
            *(uint4*)&As[r][u * 8] = ra[i];
        }
#pragma unroll
        for (int i = 0; i < BITER; i++) {
            int idx = tid + i * 256;
            int n = idx >> 2, u = idx & 3;
            *(uint4*)&Bs_hi[n][u * 8] = rbh[i];
            *(uint4*)&Bs_lo[n][u * 8] = rbl[i];
        }
        __syncthreads();
        if (t < 7) { loadA(kb + 32); loadB(kb + 32); }

#pragma unroll
        for (int kk = 0; kk < 2; kk++) {
            uint32_t koff = kk * 32;
            uint32_t a[2][4];
#pragma unroll
            for (int mi = 0; mi < 2; mi++)
                ldsm4(a[mi], aAddr + mi * (16 * BKP * 2) + koff);
#pragma unroll
            for (int nj = 0; nj < NF / 2; nj++) {
                uint32_t bh[4], bl[4];
                ldsm4(bh, bAddrHi + nj * (16 * BKP * 2) + koff);
                ldsm4(bl, bAddrLo + nj * (16 * BKP * 2) + koff);
#pragma unroll
                for (int hh = 0; hh < 2; hh++) {
                    int ni = nj * 2 + hh;
#pragma unroll
                    for (int mi = 0; mi < 2; mi++) {
                        mma16816(c[mi][ni], a[mi], bh + hh * 2);
                        mma16816(c[mi][ni], a[mi], bl + hh * 2);
                    }
                }
            }
        }
    }

    // ---- epilogue ----
#pragma unroll
    for (int mi = 0; mi < 2; mi++) {
        int r0 = rowBase + wm * 32 + mi * 16 + qrow;
#pragma unroll
        for (int ni = 0; ni < NF; ni++) {
            int col = wn * HN + ni * 8 + qk2;   // even
            float b0 = (col < NOUT) ? bias[col] : 0.f;
            float b1 = (col + 1 < NOUT) ? bias[col + 1] : 0.f;
            float v0 = c[mi][ni][0] + b0, v1 = c[mi][ni][1] + b1;
            float v2 = c[mi][ni][2] + b0, v3 = c[mi][ni][3] + b1;
            if (RELU) {
                v0 = fmaxf(v0, 0.f); v1 = fmaxf(v1, 0.f);
                v2 = fmaxf(v2, 0.f); v3 = fmaxf(v3, 0.f);
            }
            if (OUTP) {
                if (r0 < N_NODES)
                    out16[(size_t)r0 * 64 + (col >> 1)] = pack_h2(v0, v1);
                if (r0 + 8 < N_NODES)
                    out16[(size_t)(r0 + 8) * 64 + (col >> 1)] = pack_h2(v2, v3);
            } else {
                if (r0 < N_NODES) {
                    if (col < NOUT)     outf[(size_t)r0 * NOUT + col]     = v0;
                    if (col + 1 < NOUT) outf[(size_t)r0 * NOUT + col + 1] = v1;
                }
                if (r0 + 8 < N_NODES) {
                    if (col < NOUT)     outf[(size_t)(r0 + 8) * NOUT + col]     = v2;
                    if (col + 1 < NOUT) outf[(size_t)(r0 + 8) * NOUT + col + 1] = v3;
                }
            }
        }
    }
}

// ---------------- launch ----------------

extern "C" void kernel_launch(void* const* d_in, const int* in_sizes, int n_in,
                              void* d_out, int out_size) {
    const float* x   = (const float*)d_in[0];
    const int*   src = (const int*)d_in[1];
    const int*   dst = (const int*)d_in[2];
    const float* ws1 = (const float*)d_in[3];
    const float* wn1 = (const float*)d_in[4];
    const float* b1  = (const float*)d_in[5];
    const float* ws2 = (const float*)d_in[6];
    const float* wn2 = (const float*)d_in[7];
    const float* b2  = (const float*)d_in[8];
    const float* ws3 = (const float*)d_in[9];
    const float* wn3 = (const float*)d_in[10];
    const float* b3  = (const float*)d_in[11];
    float* out = (float*)d_out;

    void *px16, *pf0, *pf1, *pcur;
    void *pb1h, *pb1l, *pb2h, *pb2l, *pb3h, *pb3l;
    cudaGetSymbolAddress(&px16, g_x16);
    cudaGetSymbolAddress(&pf0, g_f0);
    cudaGetSymbolAddress(&pf1, g_f1);
    cudaGetSymbolAddress(&pcur, g_cursor);
    cudaGetSymbolAddress(&pb1h, g_B1hi);
    cudaGetSymbolAddress(&pb1l, g_B1lo);
    cudaGetSymbolAddress(&pb2h, g_B2hi);
    cudaGetSymbolAddress(&pb2l, g_B2lo);
    cudaGetSymbolAddress(&pb3h, g_B3hi);
    cudaGetSymbolAddress(&pb3l, g_B3lo);
    uint32_t* x16 = (uint32_t*)px16;
    uint32_t* f0 = (uint32_t*)pf0;
    uint32_t* f1 = (uint32_t*)pf1;

    const int EB = (N_EDGES + 255) / 256;
    const int AGG_B = (N_NODES * 32 + 255) / 256;
    const int GEMM_B = (N_NODES + 127) / 128;

    // CSR build (cursor zeroed via async memset); count fused with x->fp16 convert
    cudaMemsetAsync(pcur, 0, N_NODES * sizeof(int));
    count_cvt_k<<<EB, 256>>>(dst, x);
    scan_k<<<1, 1024>>>();
    bucket_k<<<EB, 256>>>(src, dst);

    // Layer 1
    agg_k<<<AGG_B, 256>>>(x16);
    prepB_all<<<(81920 + 255) / 256, 256>>>(ws1, wn1, ws2, wn2, ws3, wn3);
    gemm_mma<128, 128, true, true><<<GEMM_B, 256>>>(
        x16, (const uint32_t*)pb1h, (const uint32_t*)pb1l, b1, nullptr, f0);

    // Layer 2
    agg_k<<<AGG_B, 256>>>(f0);
    gemm_mma<128, 128, true, true><<<GEMM_B, 256>>>(
        f0, (const uint32_t*)pb2h, (const uint32_t*)pb2l, b2, nullptr, f1);

    // Layer 3
    agg_k<<<AGG_B, 256>>>(f1);
    gemm_mma<64, N_OUT, false, false><<<GEMM_B, 256>>>(
        f1, (const uint32_t*)pb3h, (const uint32_t*)pb3l, b3, out, nullptr);
}